// round 15
// baseline (speedup 1.0000x reference)
#include <cuda_runtime.h>
#include <cuda_bf16.h>
#include <cstdint>

// DotProductAttention, sm_103 generic PTX path -> mma.sync (HMMA) FlashAttention.
// R14: valid_lens chunk skipping — only ceil(len/64) kv-chunks are processed
// (len==0 -> all 4, matching reference's uniform softmax over -1e6 scores).
// Exact: masked-out chunks contribute p=0. E[work] = 62.5% of full loop.
// 512 threads/CTA (16 warps) x 16 q-rows/warp, 1 batch/CTA, kv chunks of 64.
// bf16 3-split (HH+HL+LH) for S=QK^T and O=PV; fp32 accumulate; log2-domain softmax.

namespace {

constexpr int SMEM_BYTES = 6 * 32768;   // QH QL KH KL VH VL, each 256x64 bf16 (128B rows)
constexpr float LOG2E   = 1.4426950408889634f;
constexpr float QSCL    = 0.125f * LOG2E;   // folded into Q at preprocess
constexpr float NEG_BIG = -1442695.04f;     // -1e6 * log2e

#define SW(o) ((o) ^ ((((uint32_t)(o)) >> 3) & 0x70u))

__device__ __forceinline__ uint32_t smem_u32(const void* p) {
    uint32_t a;
    asm("{ .reg .u64 t; cvta.to.shared.u64 t, %1; cvt.u32.u64 %0, t; }" : "=r"(a) : "l"(p));
    return a;
}
__device__ __forceinline__ void ldsm4(uint32_t r[4], uint32_t a) {
    asm volatile("ldmatrix.sync.aligned.m8n8.x4.shared.b16 {%0,%1,%2,%3}, [%4];"
                 : "=r"(r[0]), "=r"(r[1]), "=r"(r[2]), "=r"(r[3]) : "r"(a));
}
__device__ __forceinline__ void ldsm4t(uint32_t r[4], uint32_t a) {
    asm volatile("ldmatrix.sync.aligned.m8n8.x4.trans.shared.b16 {%0,%1,%2,%3}, [%4];"
                 : "=r"(r[0]), "=r"(r[1]), "=r"(r[2]), "=r"(r[3]) : "r"(a));
}
__device__ __forceinline__ void mmabf(float c[4], const uint32_t a[4], uint32_t b0, uint32_t b1) {
    asm volatile("mma.sync.aligned.m16n8k16.row.col.f32.bf16.bf16.f32 "
                 "{%0,%1,%2,%3}, {%4,%5,%6,%7}, {%8,%9}, {%0,%1,%2,%3};"
                 : "+f"(c[0]), "+f"(c[1]), "+f"(c[2]), "+f"(c[3])
                 : "r"(a[0]), "r"(a[1]), "r"(a[2]), "r"(a[3]), "r"(b0), "r"(b1));
}
// packed bf16x2: low half = bf16(lo), high half = bf16(hi)
__device__ __forceinline__ uint32_t cvt2(float lo, float hi) {
    uint32_t r;
    asm("cvt.rn.bf16x2.f32 %0, %1, %2;" : "=r"(r) : "f"(hi), "f"(lo));
    return r;
}
__device__ __forceinline__ float ex2(float x) {
    float y;
    asm("ex2.approx.f32 %0, %1;" : "=f"(y) : "f"(x));
    return y;
}
// split two floats into packed bf16 hi pair + residual lo pair
__device__ __forceinline__ void split2(float a, float b, uint32_t& hi, uint32_t& lo) {
    hi = cvt2(a, b);
    float ra = a - __uint_as_float(hi << 16);
    float rb = b - __uint_as_float(hi & 0xFFFF0000u);
    lo = cvt2(ra, rb);
}

__global__ __launch_bounds__(512, 1)
void attn_mma(const float* __restrict__ Qg, const float* __restrict__ Kg,
              const float* __restrict__ Vg, const int*   __restrict__ Lg,
              const float* __restrict__ Wg, float* __restrict__ Og)
{
    extern __shared__ char smem[];
    char* sQHp = smem;             char* sQLp = smem + 32768;
    char* sKHp = smem + 65536;     char* sKLp = smem + 98304;
    char* sVHp = smem + 131072;    char* sVLp = smem + 163840;

    const int tid = threadIdx.x, wid = tid >> 5, lane = tid & 31;
    const int b   = blockIdx.x;
    const int w   = (b >> 3) & 63;
    const int len = Lg[b];
    const int q0w = wid * 16;
    const int rg  = lane >> 2, cp = lane & 3;

    // Number of kv-chunks that can contribute. len==0 -> all scores masked
    // uniformly (-1e6) -> reference softmax is uniform over ALL 256 kv -> must
    // process all chunks (p=1 everywhere falls out of the NEG_BIG path).
    const int nch = (len == 0) ? 4 : ((len + 63) >> 6);

    // ---------- preprocess: fp32 -> bf16 hi/lo into SW128 smem (Q pre-scaled) ----------
    {
        const float4* Q4 = (const float4*)(Qg + (size_t)b * 16384);
        const float4* K4 = (const float4*)(Kg + (size_t)b * 16384);
        const float4* V4 = (const float4*)(Vg + (size_t)b * 16384);
        #pragma unroll
        for (int it = 0; it < 8; ++it) {
            int idx = tid + it * 512;
            int r = idx >> 4, c4 = idx & 15;
            uint32_t off = SW((uint32_t)(r * 128 + c4 * 8));
            uint32_t h0, l0, h1, l1;
            float4 q = Q4[idx];
            split2(q.x * QSCL, q.y * QSCL, h0, l0);
            split2(q.z * QSCL, q.w * QSCL, h1, l1);
            *(uint2*)(sQHp + off) = make_uint2(h0, h1);
            *(uint2*)(sQLp + off) = make_uint2(l0, l1);
            float4 k = K4[idx];
            split2(k.x, k.y, h0, l0); split2(k.z, k.w, h1, l1);
            *(uint2*)(sKHp + off) = make_uint2(h0, h1);
            *(uint2*)(sKLp + off) = make_uint2(l0, l1);
            float4 v = V4[idx];
            split2(v.x, v.y, h0, l0); split2(v.z, v.w, h1, l1);
            *(uint2*)(sVHp + off) = make_uint2(h0, h1);
            *(uint2*)(sVLp + off) = make_uint2(l0, l1);
        }
    }
    __syncthreads();

    const uint32_t sQH = smem_u32(sQHp), sQL = smem_u32(sQLp);
    const uint32_t sKH = smem_u32(sKHp), sKL = smem_u32(sKLp);
    const uint32_t sVH = smem_u32(sVHp), sVL = smem_u32(sVLp);

    const uint32_t qrowb = (uint32_t)((q0w + (lane & 15)) * 128 + ((lane >> 4) & 1) * 16);
    const uint32_t krowb = (uint32_t)((((lane & 7) + ((lane >> 4) & 1) * 8)) * 128 + ((lane >> 3) & 1) * 16);
    const uint32_t vrowb = (uint32_t)((((lane & 7) + ((lane >> 3) & 1) * 8)) * 128 + ((lane >> 4) & 1) * 16);

    float oa[8][4];
    #pragma unroll
    for (int dt = 0; dt < 8; ++dt)
        #pragma unroll
        for (int i = 0; i < 4; ++i) oa[dt][i] = 0.0f;

    float mrow[2] = {-1e30f, -1e30f};
    float lrow[2] = {0.0f, 0.0f};

    const float* Wb = Wg + (size_t)(w * 256) * 256;
    const int r0 = q0w + rg;

    #pragma unroll 1
    for (int c = 0; c < nch; ++c) {
        const int kvb = c * 64;

        // ---------- init S accumulators with window_mask*log2e (early LDGs) ----------
        float sa[8][4];
        #pragma unroll
        for (int nt = 0; nt < 8; ++nt) {
            const int col = kvb + nt * 8 + cp * 2;
            float2 w0 = *(const float2*)(Wb + (size_t)r0 * 256 + col);
            float2 w1 = *(const float2*)(Wb + (size_t)(r0 + 8) * 256 + col);
            sa[nt][0] = w0.x * LOG2E;
            sa[nt][1] = w0.y * LOG2E;
            sa[nt][2] = w1.x * LOG2E;
            sa[nt][3] = w1.y * LOG2E;
        }

        // ---------- S += Q K^T, bf16 3-split, pass-ordered ----------
        #pragma unroll
        for (int ks = 0; ks < 4; ++ks) {
            uint32_t aH[4], aL[4], bh[4][4], bl[4][4];
            {
                uint32_t off = SW(qrowb + (uint32_t)(ks * 32));
                ldsm4(aH, sQH + off);
                ldsm4(aL, sQL + off);
            }
            #pragma unroll
            for (int np = 0; np < 4; ++np) {
                uint32_t off = SW(krowb + (uint32_t)((kvb + np * 16) * 128 + ks * 32));
                ldsm4(bh[np], sKH + off);
                ldsm4(bl[np], sKL + off);
            }
            #pragma unroll
            for (int np = 0; np < 4; ++np) {
                mmabf(sa[2 * np],     aH, bh[np][0], bh[np][1]);
                mmabf(sa[2 * np + 1], aH, bh[np][2], bh[np][3]);
            }
            #pragma unroll
            for (int np = 0; np < 4; ++np) {
                mmabf(sa[2 * np],     aL, bh[np][0], bh[np][1]);
                mmabf(sa[2 * np + 1], aL, bh[np][2], bh[np][3]);
            }
            #pragma unroll
            for (int np = 0; np < 4; ++np) {
                mmabf(sa[2 * np],     aH, bl[np][0], bl[np][1]);
                mmabf(sa[2 * np + 1], aH, bl[np][2], bl[np][3]);
            }
        }

        // ---------- valid mask + chunk max ----------
        float mc[2] = {-1e30f, -1e30f};
        #pragma unroll
        for (int nt = 0; nt < 8; ++nt) {
            const int col = kvb + nt * 8 + cp * 2;
            if (col >= len)     { sa[nt][0] = NEG_BIG; sa[nt][2] = NEG_BIG; }
            if (col + 1 >= len) { sa[nt][1] = NEG_BIG; sa[nt][3] = NEG_BIG; }
            mc[0] = fmaxf(mc[0], fmaxf(sa[nt][0], sa[nt][1]));
            mc[1] = fmaxf(mc[1], fmaxf(sa[nt][2], sa[nt][3]));
        }

        // ---------- online softmax update ----------
        float scl[2];
        #pragma unroll
        for (int h = 0; h < 2; ++h) {
            float m = mc[h];
            m = fmaxf(m, __shfl_xor_sync(0xffffffffu, m, 1));
            m = fmaxf(m, __shfl_xor_sync(0xffffffffu, m, 2));
            float mn = fmaxf(mrow[h], m);
            scl[h] = ex2(mrow[h] - mn);   // 0 on first chunk
            mrow[h] = mn;
        }

        float lc[2] = {0.0f, 0.0f};
        #pragma unroll
        for (int nt = 0; nt < 8; ++nt) {
            float p0 = ex2(sa[nt][0] - mrow[0]);
            float p1 = ex2(sa[nt][1] - mrow[0]);
            float p2 = ex2(sa[nt][2] - mrow[1]);
            float p3 = ex2(sa[nt][3] - mrow[1]);
            sa[nt][0] = p0; sa[nt][1] = p1;
            sa[nt][2] = p2; sa[nt][3] = p3;
            lc[0] += p0 + p1;
            lc[1] += p2 + p3;
        }
        #pragma unroll
        for (int h = 0; h < 2; ++h) {
            float l = lc[h];
            l += __shfl_xor_sync(0xffffffffu, l, 1);
            l += __shfl_xor_sync(0xffffffffu, l, 2);
            lrow[h] = lrow[h] * scl[h] + l;
        }
        #pragma unroll
        for (int dt = 0; dt < 8; ++dt) {
            oa[dt][0] *= scl[0];
            oa[dt][1] *= scl[0];
            oa[dt][2] *= scl[1];
            oa[dt][3] *= scl[1];
        }

        // ---------- O += P V, bf16 3-split, pass-ordered ----------
        #pragma unroll
        for (int kk = 0; kk < 4; ++kk) {
            uint32_t vh[4][4], vl[4][4];
            #pragma unroll
            for (int dp = 0; dp < 4; ++dp) {
                uint32_t off = SW(vrowb + (uint32_t)((kvb + kk * 16) * 128 + dp * 32));
                ldsm4t(vh[dp], sVH + off);
                ldsm4t(vl[dp], sVL + off);
            }
            uint32_t paH[4], paL[4];
            #pragma unroll
            for (int j = 0; j < 2; ++j) {
                const float* p = sa[2 * kk + j];
                split2(p[0], p[1], paH[2 * j],     paL[2 * j]);
                split2(p[2], p[3], paH[2 * j + 1], paL[2 * j + 1]);
            }
            #pragma unroll
            for (int dp = 0; dp < 4; ++dp) {
                mmabf(oa[2 * dp],     paH, vh[dp][0], vh[dp][1]);
                mmabf(oa[2 * dp + 1], paH, vh[dp][2], vh[dp][3]);
            }
            #pragma unroll
            for (int dp = 0; dp < 4; ++dp) {
                mmabf(oa[2 * dp],     paL, vh[dp][0], vh[dp][1]);
                mmabf(oa[2 * dp + 1], paL, vh[dp][2], vh[dp][3]);
            }
            #pragma unroll
            for (int dp = 0; dp < 4; ++dp) {
                mmabf(oa[2 * dp],     paH, vl[dp][0], vl[dp][1]);
                mmabf(oa[2 * dp + 1], paH, vl[dp][2], vl[dp][3]);
            }
        }
    }

    // ---------- finalize: O /= l, store fp32 ----------
    float corr[2] = {1.0f / lrow[0], 1.0f / lrow[1]};

    float* Ob = Og + (size_t)b * 16384;
    #pragma unroll
    for (int dt = 0; dt < 8; ++dt) {
        const int colo = dt * 8 + cp * 2;
        *(float2*)(Ob + (size_t)r0 * 64 + colo) =
            make_float2(oa[dt][0] * corr[0], oa[dt][1] * corr[0]);
        *(float2*)(Ob + (size_t)(r0 + 8) * 64 + colo) =
            make_float2(oa[dt][2] * corr[1], oa[dt][3] * corr[1]);
    }
}

} // namespace

extern "C" void kernel_launch(void* const* d_in, const int* in_sizes, int n_in,
                              void* d_out, int out_size)
{
    const float* Q = (const float*)d_in[0];
    const float* K = (const float*)d_in[1];
    const float* V = (const float*)d_in[2];
    const int*   L = (const int*)  d_in[3];
    const float* W = (const float*)d_in[4];
    float*       O = (float*)d_out;

    const int n = in_sizes[0] / (256 * 64);   // 2048 batches

    cudaFuncSetAttribute(attn_mma, cudaFuncAttributeMaxDynamicSharedMemorySize, SMEM_BYTES);
    attn_mma<<<n, 512, SMEM_BYTES>>>(Q, K, V, L, W, O);
}

// round 16
// speedup vs baseline: 1.7481x; 1.7481x over previous
#include <cuda_runtime.h>
#include <cuda_bf16.h>
#include <cstdint>

// DotProductAttention, sm_103 generic PTX path -> mma.sync (HMMA) FlashAttention.
// R16: O = P·V collapsed to ONE fp16 MMA pass (P in (0,1], V ~ N(0,1): fp16-safe;
// rel_err budget ~3e-4 << 1e-3). S = Q K^T stays bf16 3-split. VL buffer removed
// (smem 160KB). valid_lens chunk skip retained.
// 512 threads/CTA (16 warps) x 16 q-rows/warp, 1 batch/CTA, kv chunks of 64.

namespace {

constexpr int SMEM_BYTES = 5 * 32768;   // QH QL KH KL VF, each 256x64 x16bit (128B rows)
constexpr float LOG2E   = 1.4426950408889634f;
constexpr float QSCL    = 0.125f * LOG2E;   // folded into Q at preprocess
constexpr float NEG_BIG = -1442695.04f;     // -1e6 * log2e

#define SW(o) ((o) ^ ((((uint32_t)(o)) >> 3) & 0x70u))

__device__ __forceinline__ uint32_t smem_u32(const void* p) {
    uint32_t a;
    asm("{ .reg .u64 t; cvta.to.shared.u64 t, %1; cvt.u32.u64 %0, t; }" : "=r"(a) : "l"(p));
    return a;
}
__device__ __forceinline__ void ldsm4(uint32_t r[4], uint32_t a) {
    asm volatile("ldmatrix.sync.aligned.m8n8.x4.shared.b16 {%0,%1,%2,%3}, [%4];"
                 : "=r"(r[0]), "=r"(r[1]), "=r"(r[2]), "=r"(r[3]) : "r"(a));
}
__device__ __forceinline__ void ldsm4t(uint32_t r[4], uint32_t a) {
    asm volatile("ldmatrix.sync.aligned.m8n8.x4.trans.shared.b16 {%0,%1,%2,%3}, [%4];"
                 : "=r"(r[0]), "=r"(r[1]), "=r"(r[2]), "=r"(r[3]) : "r"(a));
}
__device__ __forceinline__ void mmabf(float c[4], const uint32_t a[4], uint32_t b0, uint32_t b1) {
    asm volatile("mma.sync.aligned.m16n8k16.row.col.f32.bf16.bf16.f32 "
                 "{%0,%1,%2,%3}, {%4,%5,%6,%7}, {%8,%9}, {%0,%1,%2,%3};"
                 : "+f"(c[0]), "+f"(c[1]), "+f"(c[2]), "+f"(c[3])
                 : "r"(a[0]), "r"(a[1]), "r"(a[2]), "r"(a[3]), "r"(b0), "r"(b1));
}
__device__ __forceinline__ void mmaf16(float c[4], const uint32_t a[4], uint32_t b0, uint32_t b1) {
    asm volatile("mma.sync.aligned.m16n8k16.row.col.f32.f16.f16.f32 "
                 "{%0,%1,%2,%3}, {%4,%5,%6,%7}, {%8,%9}, {%0,%1,%2,%3};"
                 : "+f"(c[0]), "+f"(c[1]), "+f"(c[2]), "+f"(c[3])
                 : "r"(a[0]), "r"(a[1]), "r"(a[2]), "r"(a[3]), "r"(b0), "r"(b1));
}
// packed bf16x2: low half = bf16(lo), high half = bf16(hi)
__device__ __forceinline__ uint32_t cvt2(float lo, float hi) {
    uint32_t r;
    asm("cvt.rn.bf16x2.f32 %0, %1, %2;" : "=r"(r) : "f"(hi), "f"(lo));
    return r;
}
// packed fp16x2
__device__ __forceinline__ uint32_t cvt2h(float lo, float hi) {
    uint32_t r;
    asm("cvt.rn.f16x2.f32 %0, %1, %2;" : "=r"(r) : "f"(hi), "f"(lo));
    return r;
}
__device__ __forceinline__ float ex2(float x) {
    float y;
    asm("ex2.approx.f32 %0, %1;" : "=f"(y) : "f"(x));
    return y;
}
// split two floats into packed bf16 hi pair + residual lo pair
__device__ __forceinline__ void split2(float a, float b, uint32_t& hi, uint32_t& lo) {
    hi = cvt2(a, b);
    float ra = a - __uint_as_float(hi << 16);
    float rb = b - __uint_as_float(hi & 0xFFFF0000u);
    lo = cvt2(ra, rb);
}

__global__ __launch_bounds__(512, 1)
void attn_mma(const float* __restrict__ Qg, const float* __restrict__ Kg,
              const float* __restrict__ Vg, const int*   __restrict__ Lg,
              const float* __restrict__ Wg, float* __restrict__ Og)
{
    extern __shared__ char smem[];
    char* sQHp = smem;             char* sQLp = smem + 32768;
    char* sKHp = smem + 65536;     char* sKLp = smem + 98304;
    char* sVFp = smem + 131072;    // V as plain fp16

    const int tid = threadIdx.x, wid = tid >> 5, lane = tid & 31;
    const int b   = blockIdx.x;
    const int w   = (b >> 3) & 63;
    const int len = Lg[b];
    const int q0w = wid * 16;
    const int rg  = lane >> 2, cp = lane & 3;

    // kv-chunks that can contribute (len==0 -> uniform softmax over all 256).
    const int nch = (len == 0) ? 4 : ((len + 63) >> 6);

    // ---------- preprocess: Q/K -> bf16 hi/lo, V -> fp16, SW128 smem ----------
    {
        const float4* Q4 = (const float4*)(Qg + (size_t)b * 16384);
        const float4* K4 = (const float4*)(Kg + (size_t)b * 16384);
        const float4* V4 = (const float4*)(Vg + (size_t)b * 16384);
        #pragma unroll
        for (int it = 0; it < 8; ++it) {
            int idx = tid + it * 512;
            int r = idx >> 4, c4 = idx & 15;
            uint32_t off = SW((uint32_t)(r * 128 + c4 * 8));
            uint32_t h0, l0, h1, l1;
            float4 q = Q4[idx];
            split2(q.x * QSCL, q.y * QSCL, h0, l0);
            split2(q.z * QSCL, q.w * QSCL, h1, l1);
            *(uint2*)(sQHp + off) = make_uint2(h0, h1);
            *(uint2*)(sQLp + off) = make_uint2(l0, l1);
            float4 k = K4[idx];
            split2(k.x, k.y, h0, l0); split2(k.z, k.w, h1, l1);
            *(uint2*)(sKHp + off) = make_uint2(h0, h1);
            *(uint2*)(sKLp + off) = make_uint2(l0, l1);
            float4 v = V4[idx];
            *(uint2*)(sVFp + off) = make_uint2(cvt2h(v.x, v.y), cvt2h(v.z, v.w));
        }
    }
    __syncthreads();

    const uint32_t sQH = smem_u32(sQHp), sQL = smem_u32(sQLp);
    const uint32_t sKH = smem_u32(sKHp), sKL = smem_u32(sKLp);
    const uint32_t sVF = smem_u32(sVFp);

    const uint32_t qrowb = (uint32_t)((q0w + (lane & 15)) * 128 + ((lane >> 4) & 1) * 16);
    const uint32_t krowb = (uint32_t)((((lane & 7) + ((lane >> 4) & 1) * 8)) * 128 + ((lane >> 3) & 1) * 16);
    const uint32_t vrowb = (uint32_t)((((lane & 7) + ((lane >> 3) & 1) * 8)) * 128 + ((lane >> 4) & 1) * 16);

    float oa[8][4];
    #pragma unroll
    for (int dt = 0; dt < 8; ++dt)
        #pragma unroll
        for (int i = 0; i < 4; ++i) oa[dt][i] = 0.0f;

    float mrow[2] = {-1e30f, -1e30f};
    float lrow[2] = {0.0f, 0.0f};

    const float* Wb = Wg + (size_t)(w * 256) * 256;
    const int r0 = q0w + rg;

    #pragma unroll 1
    for (int c = 0; c < nch; ++c) {
        const int kvb = c * 64;

        // ---------- init S accumulators with window_mask*log2e (early LDGs) ----------
        float sa[8][4];
        #pragma unroll
        for (int nt = 0; nt < 8; ++nt) {
            const int col = kvb + nt * 8 + cp * 2;
            float2 w0 = *(const float2*)(Wb + (size_t)r0 * 256 + col);
            float2 w1 = *(const float2*)(Wb + (size_t)(r0 + 8) * 256 + col);
            sa[nt][0] = w0.x * LOG2E;
            sa[nt][1] = w0.y * LOG2E;
            sa[nt][2] = w1.x * LOG2E;
            sa[nt][3] = w1.y * LOG2E;
        }

        // ---------- S += Q K^T, bf16 3-split, pass-ordered ----------
        #pragma unroll
        for (int ks = 0; ks < 4; ++ks) {
            uint32_t aH[4], aL[4], bh[4][4], bl[4][4];
            {
                uint32_t off = SW(qrowb + (uint32_t)(ks * 32));
                ldsm4(aH, sQH + off);
                ldsm4(aL, sQL + off);
            }
            #pragma unroll
            for (int np = 0; np < 4; ++np) {
                uint32_t off = SW(krowb + (uint32_t)((kvb + np * 16) * 128 + ks * 32));
                ldsm4(bh[np], sKH + off);
                ldsm4(bl[np], sKL + off);
            }
            #pragma unroll
            for (int np = 0; np < 4; ++np) {
                mmabf(sa[2 * np],     aH, bh[np][0], bh[np][1]);
                mmabf(sa[2 * np + 1], aH, bh[np][2], bh[np][3]);
            }
            #pragma unroll
            for (int np = 0; np < 4; ++np) {
                mmabf(sa[2 * np],     aL, bh[np][0], bh[np][1]);
                mmabf(sa[2 * np + 1], aL, bh[np][2], bh[np][3]);
            }
            #pragma unroll
            for (int np = 0; np < 4; ++np) {
                mmabf(sa[2 * np],     aH, bl[np][0], bl[np][1]);
                mmabf(sa[2 * np + 1], aH, bl[np][2], bl[np][3]);
            }
        }

        // ---------- valid mask + chunk max ----------
        float mc[2] = {-1e30f, -1e30f};
        #pragma unroll
        for (int nt = 0; nt < 8; ++nt) {
            const int col = kvb + nt * 8 + cp * 2;
            if (col >= len)     { sa[nt][0] = NEG_BIG; sa[nt][2] = NEG_BIG; }
            if (col + 1 >= len) { sa[nt][1] = NEG_BIG; sa[nt][3] = NEG_BIG; }
            mc[0] = fmaxf(mc[0], fmaxf(sa[nt][0], sa[nt][1]));
            mc[1] = fmaxf(mc[1], fmaxf(sa[nt][2], sa[nt][3]));
        }

        // ---------- online softmax update ----------
        float scl[2];
        #pragma unroll
        for (int h = 0; h < 2; ++h) {
            float m = mc[h];
            m = fmaxf(m, __shfl_xor_sync(0xffffffffu, m, 1));
            m = fmaxf(m, __shfl_xor_sync(0xffffffffu, m, 2));
            float mn = fmaxf(mrow[h], m);
            scl[h] = ex2(mrow[h] - mn);   // 0 on first chunk
            mrow[h] = mn;
        }

        float lc[2] = {0.0f, 0.0f};
        #pragma unroll
        for (int nt = 0; nt < 8; ++nt) {
            float p0 = ex2(sa[nt][0] - mrow[0]);
            float p1 = ex2(sa[nt][1] - mrow[0]);
            float p2 = ex2(sa[nt][2] - mrow[1]);
            float p3 = ex2(sa[nt][3] - mrow[1]);
            sa[nt][0] = p0; sa[nt][1] = p1;
            sa[nt][2] = p2; sa[nt][3] = p3;
            lc[0] += p0 + p1;
            lc[1] += p2 + p3;
        }
        #pragma unroll
        for (int h = 0; h < 2; ++h) {
            float l = lc[h];
            l += __shfl_xor_sync(0xffffffffu, l, 1);
            l += __shfl_xor_sync(0xffffffffu, l, 2);
            lrow[h] = lrow[h] * scl[h] + l;
        }
        #pragma unroll
        for (int dt = 0; dt < 8; ++dt) {
            oa[dt][0] *= scl[0];
            oa[dt][1] *= scl[0];
            oa[dt][2] *= scl[1];
            oa[dt][3] *= scl[1];
        }

        // ---------- O += P V : single fp16 pass (P in (0,1], V ~ N(0,1)) ----------
        #pragma unroll
        for (int kk = 0; kk < 4; ++kk) {
            uint32_t vf[4][4];
            #pragma unroll
            for (int dp = 0; dp < 4; ++dp) {
                uint32_t off = SW(vrowb + (uint32_t)((kvb + kk * 16) * 128 + dp * 32));
                ldsm4t(vf[dp], sVF + off);
            }
            uint32_t pa[4];
            #pragma unroll
            for (int j = 0; j < 2; ++j) {
                const float* p = sa[2 * kk + j];
                pa[2 * j]     = cvt2h(p[0], p[1]);
                pa[2 * j + 1] = cvt2h(p[2], p[3]);
            }
            #pragma unroll
            for (int dp = 0; dp < 4; ++dp) {
                mmaf16(oa[2 * dp],     pa, vf[dp][0], vf[dp][1]);
                mmaf16(oa[2 * dp + 1], pa, vf[dp][2], vf[dp][3]);
            }
        }
    }

    // ---------- finalize: O /= l, store fp32 ----------
    float corr[2] = {1.0f / lrow[0], 1.0f / lrow[1]};

    float* Ob = Og + (size_t)b * 16384;
    #pragma unroll
    for (int dt = 0; dt < 8; ++dt) {
        const int colo = dt * 8 + cp * 2;
        *(float2*)(Ob + (size_t)r0 * 64 + colo) =
            make_float2(oa[dt][0] * corr[0], oa[dt][1] * corr[0]);
        *(float2*)(Ob + (size_t)(r0 + 8) * 64 + colo) =
            make_float2(oa[dt][2] * corr[1], oa[dt][3] * corr[1]);
    }
}

} // namespace

extern "C" void kernel_launch(void* const* d_in, const int* in_sizes, int n_in,
                              void* d_out, int out_size)
{
    const float* Q = (const float*)d_in[0];
    const float* K = (const float*)d_in[1];
    const float* V = (const float*)d_in[2];
    const int*   L = (const int*)  d_in[3];
    const float* W = (const float*)d_in[4];
    float*       O = (float*)d_out;

    const int n = in_sizes[0] / (256 * 64);   // 2048 batches

    cudaFuncSetAttribute(attn_mma, cudaFuncAttributeMaxDynamicSharedMemorySize, SMEM_BYTES);
    attn_mma<<<n, 512, SMEM_BYTES>>>(Q, K, V, L, W, O);
}

// round 17
// speedup vs baseline: 2.1023x; 1.2026x over previous
#include <cuda_runtime.h>
#include <cuda_bf16.h>
#include <cuda_fp16.h>
#include <cstdint>

// DotProductAttention, sm_103 generic PTX path -> mma.sync (HMMA) FlashAttention.
// R17: S = Q K^T as fp16 2-pass (Q hi/lo split x K single fp16; K-side rounding
// ~4.9e-4 in log-score), O = P V single fp16 pass (measured 2.4e-4). Total
// rel_err budget ~5.5e-4 < 1e-3. KL buffer gone -> smem 128KB.
// 512 threads/CTA (16 warps) x 16 q-rows/warp, 1 batch/CTA, kv chunks of 64,
// valid_lens chunk skipping, log2-domain online softmax.

namespace {

constexpr int SMEM_BYTES = 4 * 32768;   // QH QL KF VF, each 256x64 x16bit (128B rows)
constexpr float LOG2E   = 1.4426950408889634f;
constexpr float QSCL    = 0.125f * LOG2E;   // folded into Q at preprocess
constexpr float NEG_BIG = -1442695.04f;     // -1e6 * log2e

#define SW(o) ((o) ^ ((((uint32_t)(o)) >> 3) & 0x70u))

__device__ __forceinline__ uint32_t smem_u32(const void* p) {
    uint32_t a;
    asm("{ .reg .u64 t; cvta.to.shared.u64 t, %1; cvt.u32.u64 %0, t; }" : "=r"(a) : "l"(p));
    return a;
}
__device__ __forceinline__ void ldsm4(uint32_t r[4], uint32_t a) {
    asm volatile("ldmatrix.sync.aligned.m8n8.x4.shared.b16 {%0,%1,%2,%3}, [%4];"
                 : "=r"(r[0]), "=r"(r[1]), "=r"(r[2]), "=r"(r[3]) : "r"(a));
}
__device__ __forceinline__ void ldsm4t(uint32_t r[4], uint32_t a) {
    asm volatile("ldmatrix.sync.aligned.m8n8.x4.trans.shared.b16 {%0,%1,%2,%3}, [%4];"
                 : "=r"(r[0]), "=r"(r[1]), "=r"(r[2]), "=r"(r[3]) : "r"(a));
}
__device__ __forceinline__ void mmaf16(float c[4], const uint32_t a[4], uint32_t b0, uint32_t b1) {
    asm volatile("mma.sync.aligned.m16n8k16.row.col.f32.f16.f16.f32 "
                 "{%0,%1,%2,%3}, {%4,%5,%6,%7}, {%8,%9}, {%0,%1,%2,%3};"
                 : "+f"(c[0]), "+f"(c[1]), "+f"(c[2]), "+f"(c[3])
                 : "r"(a[0]), "r"(a[1]), "r"(a[2]), "r"(a[3]), "r"(b0), "r"(b1));
}
// packed fp16x2: low half = fp16(lo-arg), high half = fp16(hi-arg)
__device__ __forceinline__ uint32_t cvt2h(float lo, float hi) {
    uint32_t r;
    asm("cvt.rn.f16x2.f32 %0, %1, %2;" : "=r"(r) : "f"(hi), "f"(lo));
    return r;
}
__device__ __forceinline__ float ex2(float x) {
    float y;
    asm("ex2.approx.f32 %0, %1;" : "=f"(y) : "f"(x));
    return y;
}
// split two floats into packed fp16 hi pair + fp16 residual pair
__device__ __forceinline__ void split2h(float a, float b, uint32_t& hi, uint32_t& lo) {
    hi = cvt2h(a, b);
    __half2 h = *reinterpret_cast<__half2*>(&hi);
    float ra = a - __half2float(__low2half(h));
    float rb = b - __half2float(__high2half(h));
    lo = cvt2h(ra, rb);
}

__global__ __launch_bounds__(512, 1)
void attn_mma(const float* __restrict__ Qg, const float* __restrict__ Kg,
              const float* __restrict__ Vg, const int*   __restrict__ Lg,
              const float* __restrict__ Wg, float* __restrict__ Og)
{
    extern __shared__ char smem[];
    char* sQHp = smem;             char* sQLp = smem + 32768;
    char* sKFp = smem + 65536;     char* sVFp = smem + 98304;

    const int tid = threadIdx.x, wid = tid >> 5, lane = tid & 31;
    const int b   = blockIdx.x;
    const int w   = (b >> 3) & 63;
    const int len = Lg[b];
    const int q0w = wid * 16;
    const int rg  = lane >> 2, cp = lane & 3;

    // kv-chunks that can contribute (len==0 -> uniform softmax over all 256).
    const int nch = (len == 0) ? 4 : ((len + 63) >> 6);

    // ---------- preprocess: Q -> fp16 hi/lo (pre-scaled), K/V -> fp16, SW128 ----------
    {
        const float4* Q4 = (const float4*)(Qg + (size_t)b * 16384);
        const float4* K4 = (const float4*)(Kg + (size_t)b * 16384);
        const float4* V4 = (const float4*)(Vg + (size_t)b * 16384);
        #pragma unroll
        for (int it = 0; it < 8; ++it) {
            int idx = tid + it * 512;
            int r = idx >> 4, c4 = idx & 15;
            uint32_t off = SW((uint32_t)(r * 128 + c4 * 8));
            uint32_t h0, l0, h1, l1;
            float4 q = Q4[idx];
            split2h(q.x * QSCL, q.y * QSCL, h0, l0);
            split2h(q.z * QSCL, q.w * QSCL, h1, l1);
            *(uint2*)(sQHp + off) = make_uint2(h0, h1);
            *(uint2*)(sQLp + off) = make_uint2(l0, l1);
            float4 k = K4[idx];
            *(uint2*)(sKFp + off) = make_uint2(cvt2h(k.x, k.y), cvt2h(k.z, k.w));
            float4 v = V4[idx];
            *(uint2*)(sVFp + off) = make_uint2(cvt2h(v.x, v.y), cvt2h(v.z, v.w));
        }
    }
    __syncthreads();

    const uint32_t sQH = smem_u32(sQHp), sQL = smem_u32(sQLp);
    const uint32_t sKF = smem_u32(sKFp), sVF = smem_u32(sVFp);

    const uint32_t qrowb = (uint32_t)((q0w + (lane & 15)) * 128 + ((lane >> 4) & 1) * 16);
    const uint32_t krowb = (uint32_t)((((lane & 7) + ((lane >> 4) & 1) * 8)) * 128 + ((lane >> 3) & 1) * 16);
    const uint32_t vrowb = (uint32_t)((((lane & 7) + ((lane >> 3) & 1) * 8)) * 128 + ((lane >> 4) & 1) * 16);

    float oa[8][4];
    #pragma unroll
    for (int dt = 0; dt < 8; ++dt)
        #pragma unroll
        for (int i = 0; i < 4; ++i) oa[dt][i] = 0.0f;

    float mrow[2] = {-1e30f, -1e30f};
    float lrow[2] = {0.0f, 0.0f};

    const float* Wb = Wg + (size_t)(w * 256) * 256;
    const int r0 = q0w + rg;

    #pragma unroll 1
    for (int c = 0; c < nch; ++c) {
        const int kvb = c * 64;

        // ---------- init S accumulators with window_mask*log2e (early LDGs) ----------
        float sa[8][4];
        #pragma unroll
        for (int nt = 0; nt < 8; ++nt) {
            const int col = kvb + nt * 8 + cp * 2;
            float2 w0 = *(const float2*)(Wb + (size_t)r0 * 256 + col);
            float2 w1 = *(const float2*)(Wb + (size_t)(r0 + 8) * 256 + col);
            sa[nt][0] = w0.x * LOG2E;
            sa[nt][1] = w0.y * LOG2E;
            sa[nt][2] = w1.x * LOG2E;
            sa[nt][3] = w1.y * LOG2E;
        }

        // ---------- S += Q K^T, fp16 2-pass (Qh*K then Ql*K) ----------
        #pragma unroll
        for (int ks = 0; ks < 4; ++ks) {
            uint32_t aH[4], aL[4], bf[4][4];
            {
                uint32_t off = SW(qrowb + (uint32_t)(ks * 32));
                ldsm4(aH, sQH + off);
                ldsm4(aL, sQL + off);
            }
            #pragma unroll
            for (int np = 0; np < 4; ++np) {
                uint32_t off = SW(krowb + (uint32_t)((kvb + np * 16) * 128 + ks * 32));
                ldsm4(bf[np], sKF + off);
            }
            // pass 1: Qh * K
            #pragma unroll
            for (int np = 0; np < 4; ++np) {
                mmaf16(sa[2 * np],     aH, bf[np][0], bf[np][1]);
                mmaf16(sa[2 * np + 1], aH, bf[np][2], bf[np][3]);
            }
            // pass 2: Ql * K
            #pragma unroll
            for (int np = 0; np < 4; ++np) {
                mmaf16(sa[2 * np],     aL, bf[np][0], bf[np][1]);
                mmaf16(sa[2 * np + 1], aL, bf[np][2], bf[np][3]);
            }
        }

        // ---------- valid mask + chunk max ----------
        float mc[2] = {-1e30f, -1e30f};
        #pragma unroll
        for (int nt = 0; nt < 8; ++nt) {
            const int col = kvb + nt * 8 + cp * 2;
            if (col >= len)     { sa[nt][0] = NEG_BIG; sa[nt][2] = NEG_BIG; }
            if (col + 1 >= len) { sa[nt][1] = NEG_BIG; sa[nt][3] = NEG_BIG; }
            mc[0] = fmaxf(mc[0], fmaxf(sa[nt][0], sa[nt][1]));
            mc[1] = fmaxf(mc[1], fmaxf(sa[nt][2], sa[nt][3]));
        }

        // ---------- online softmax update ----------
        float scl[2];
        #pragma unroll
        for (int h = 0; h < 2; ++h) {
            float m = mc[h];
            m = fmaxf(m, __shfl_xor_sync(0xffffffffu, m, 1));
            m = fmaxf(m, __shfl_xor_sync(0xffffffffu, m, 2));
            float mn = fmaxf(mrow[h], m);
            scl[h] = ex2(mrow[h] - mn);   // 0 on first chunk
            mrow[h] = mn;
        }

        float lc[2] = {0.0f, 0.0f};
        #pragma unroll
        for (int nt = 0; nt < 8; ++nt) {
            float p0 = ex2(sa[nt][0] - mrow[0]);
            float p1 = ex2(sa[nt][1] - mrow[0]);
            float p2 = ex2(sa[nt][2] - mrow[1]);
            float p3 = ex2(sa[nt][3] - mrow[1]);
            sa[nt][0] = p0; sa[nt][1] = p1;
            sa[nt][2] = p2; sa[nt][3] = p3;
            lc[0] += p0 + p1;
            lc[1] += p2 + p3;
        }
        #pragma unroll
        for (int h = 0; h < 2; ++h) {
            float l = lc[h];
            l += __shfl_xor_sync(0xffffffffu, l, 1);
            l += __shfl_xor_sync(0xffffffffu, l, 2);
            lrow[h] = lrow[h] * scl[h] + l;
        }
        #pragma unroll
        for (int dt = 0; dt < 8; ++dt) {
            oa[dt][0] *= scl[0];
            oa[dt][1] *= scl[0];
            oa[dt][2] *= scl[1];
            oa[dt][3] *= scl[1];
        }

        // ---------- O += P V : single fp16 pass (P in (0,1], V ~ N(0,1)) ----------
        #pragma unroll
        for (int kk = 0; kk < 4; ++kk) {
            uint32_t vf[4][4];
            #pragma unroll
            for (int dp = 0; dp < 4; ++dp) {
                uint32_t off = SW(vrowb + (uint32_t)((kvb + kk * 16) * 128 + dp * 32));
                ldsm4t(vf[dp], sVF + off);
            }
            uint32_t pa[4];
            #pragma unroll
            for (int j = 0; j < 2; ++j) {
                const float* p = sa[2 * kk + j];
                pa[2 * j]     = cvt2h(p[0], p[1]);
                pa[2 * j + 1] = cvt2h(p[2], p[3]);
            }
            #pragma unroll
            for (int dp = 0; dp < 4; ++dp) {
                mmaf16(oa[2 * dp],     pa, vf[dp][0], vf[dp][1]);
                mmaf16(oa[2 * dp + 1], pa, vf[dp][2], vf[dp][3]);
            }
        }
    }

    // ---------- finalize: O /= l, store fp32 ----------
    float corr[2] = {1.0f / lrow[0], 1.0f / lrow[1]};

    float* Ob = Og + (size_t)b * 16384;
    #pragma unroll
    for (int dt = 0; dt < 8; ++dt) {
        const int colo = dt * 8 + cp * 2;
        *(float2*)(Ob + (size_t)r0 * 64 + colo) =
            make_float2(oa[dt][0] * corr[0], oa[dt][1] * corr[0]);
        *(float2*)(Ob + (size_t)(r0 + 8) * 64 + colo) =
            make_float2(oa[dt][2] * corr[1], oa[dt][3] * corr[1]);
    }
}

} // namespace

extern "C" void kernel_launch(void* const* d_in, const int* in_sizes, int n_in,
                              void* d_out, int out_size)
{
    const float* Q = (const float*)d_in[0];
    const float* K = (const float*)d_in[1];
    const float* V = (const float*)d_in[2];
    const int*   L = (const int*)  d_in[3];
    const float* W = (const float*)d_in[4];
    float*       O = (float*)d_out;

    const int n = in_sizes[0] / (256 * 64);   // 2048 batches

    cudaFuncSetAttribute(attn_mma, cudaFuncAttributeMaxDynamicSharedMemorySize, SMEM_BYTES);
    attn_mma<<<n, 512, SMEM_BYTES>>>(Q, K, V, L, W, O);
}